// round 3
// baseline (speedup 1.0000x reference)
#include <cuda_runtime.h>

#define J 256          // nb_features
#define D 64           // head_dim
#define M_TILE 64      // tokens per block
#define PITCH 68       // padded row pitch (floats) for bank-conflict-free LDS
#define THREADS 512

__device__ __forceinline__ unsigned long long lds_u64(unsigned a) {
    unsigned long long v;
    asm("ld.shared.b64 %0, [%1];" : "=l"(v) : "r"(a));
    return v;
}

__device__ __forceinline__ void ffma2(unsigned long long& d,
                                      unsigned long long a,
                                      unsigned long long b) {
    asm("fma.rn.f32x2 %0, %1, %2, %0;" : "+l"(d) : "l"(a), "l"(b));
}

__device__ __forceinline__ void unpack2(unsigned long long v, float& lo, float& hi) {
    asm("mov.b64 {%0, %1}, %2;" : "=f"(lo), "=f"(hi) : "l"(v));
}

__global__ __launch_bounds__(THREADS, 1)
void performer_kernel(const float* __restrict__ x,
                      const float* __restrict__ proj,
                      float* __restrict__ out) {
    extern __shared__ float sm[];
    // layout: ps [J][PITCH], xs [M_TILE][PITCH], sdiag [M_TILE]
    float* ps    = sm;
    float* xs    = sm + J * PITCH;
    float* sdiag = xs + M_TILE * PITCH;

    const int tid = threadIdx.x;
    const int m0  = blockIdx.x * M_TILE;

    const float NORM  = 0.3535533905932738f;  // 64^-0.25
    const float RATIO = 0.0625f;              // 256^-0.5
    const float EPSV  = 1e-4f;

    // ---- stage projection (pre-scaled by data_normalizer), coalesced ----
    #pragma unroll
    for (int r = 0; r < (J * D) / THREADS; r++) {
        int i = tid + r * THREADS;
        int j = i >> 6, k = i & 63;
        ps[j * PITCH + k] = proj[i] * NORM;
    }
    // ---- stage x tile (raw), coalesced ----
    const float* xblk = x + (size_t)m0 * D;
    #pragma unroll
    for (int r = 0; r < (M_TILE * D) / THREADS; r++) {
        int i = tid + r * THREADS;
        int t = i >> 6, k = i & 63;
        xs[t * PITCH + k] = xblk[i];
    }
    __syncthreads();

    // ---- per-token diag = 0.5 * ||x||^2 : 8 lanes per token, butterfly ----
    {
        const int t  = tid >> 3;        // token 0..63
        const int k0 = (tid & 7) * 8;   // this lane's 8-element chunk
        float s = 0.f;
        #pragma unroll
        for (int k = 0; k < 8; k++) {
            float v = xs[t * PITCH + k0 + k];
            s += v * v;
        }
        #pragma unroll
        for (int d = 4; d > 0; d >>= 1)
            s += __shfl_xor_sync(0xFFFFFFFFu, s, d);
        if ((tid & 7) == 0) sdiag[t] = 0.5f * s;
    }
    __syncthreads();

    // ---- main loop: thread tile = 8 tokens x 4 features, f32x2 along K ----
    const int lane = tid & 31;
    const int w    = tid >> 5;
    const int tg   = lane & 7;        // token group: tokens tg + 8*i
    const int jg   = lane >> 3;       // feature sub-col
    const int j0   = (w << 4) + (jg << 2);   // 4 consecutive features

    unsigned sbase;
    asm("{ .reg .u64 t; cvta.to.shared.u64 t, %1; cvt.u32.u64 %0, t; }"
        : "=r"(sbase) : "l"(sm));
    const unsigned ps_a = sbase;
    const unsigned xs_a = sbase + (unsigned)(J * PITCH) * 4u;

    unsigned long long acc[8][4];
    #pragma unroll
    for (int i = 0; i < 8; i++)
        #pragma unroll
        for (int m = 0; m < 4; m++) acc[i][m] = 0ull;

    const unsigned xaddr0 = xs_a + (unsigned)(tg * PITCH) * 4u;
    const unsigned paddr0 = ps_a + (unsigned)(j0 * PITCH) * 4u;

    #pragma unroll
    for (int kp = 0; kp < D / 2; kp++) {       // k-pair index
        const unsigned koff = (unsigned)kp * 8u;
        unsigned long long pv[4];
        #pragma unroll
        for (int m = 0; m < 4; m++)
            pv[m] = lds_u64(paddr0 + (unsigned)(m * PITCH) * 4u + koff);
        #pragma unroll
        for (int i = 0; i < 8; i++) {
            unsigned long long xv =
                lds_u64(xaddr0 + (unsigned)(i * 8 * PITCH) * 4u + koff);
            #pragma unroll
            for (int m = 0; m < 4; m++) ffma2(acc[i][m], xv, pv[m]);
        }
    }

    // ---- epilogue: combine halves, exp, float4 store ----
    #pragma unroll
    for (int i = 0; i < 8; i++) {
        const int t = tg + 8 * i;
        const float dg = sdiag[t];
        float r[4];
        #pragma unroll
        for (int m = 0; m < 4; m++) {
            float lo, hi;
            unpack2(acc[i][m], lo, hi);
            float dd = lo + hi;
            r[m] = RATIO * (__expf(dd - dg) + EPSV);
        }
        float4 o = make_float4(r[0], r[1], r[2], r[3]);
        *reinterpret_cast<float4*>(out + (size_t)(m0 + t) * J + j0) = o;
    }
}

extern "C" void kernel_launch(void* const* d_in, const int* in_sizes, int n_in,
                              void* d_out, int out_size) {
    const float* x    = (const float*)d_in[0];   // [2,16,4096,64] fp32
    const float* proj = (const float*)d_in[1];   // [256,64] fp32
    float* out        = (float*)d_out;           // [2,16,4096,256] fp32

    const int M = in_sizes[0] / D;               // 131072 tokens
    const int grid = M / M_TILE;                 // 2048 blocks

    const int smem_bytes = (J * PITCH + M_TILE * PITCH + M_TILE) * (int)sizeof(float);
    cudaFuncSetAttribute(performer_kernel,
                         cudaFuncAttributeMaxDynamicSharedMemorySize, smem_bytes);

    performer_kernel<<<grid, THREADS, smem_bytes>>>(x, proj, out);
}

// round 4
// speedup vs baseline: 1.0327x; 1.0327x over previous
#include <cuda_runtime.h>

#define J 256          // nb_features
#define D 64           // head_dim
#define M_TILE 64      // tokens per block-tile
#define PITCH 68       // row pitch in floats (272 B, 16B-aligned, odd*16)
#define THREADS 512
#define GRID 296       // persistent: ~2 blocks/SM-slot, 2048 tiles strided

__device__ __forceinline__ void lds_v2u64(unsigned a,
                                          unsigned long long& v0,
                                          unsigned long long& v1) {
    asm("ld.shared.v2.u64 {%0, %1}, [%2];" : "=l"(v0), "=l"(v1) : "r"(a));
}

__device__ __forceinline__ void ffma2(unsigned long long& d,
                                      unsigned long long a,
                                      unsigned long long b) {
    asm("fma.rn.f32x2 %0, %1, %2, %0;" : "+l"(d) : "l"(a), "l"(b));
}

__device__ __forceinline__ void unpack2(unsigned long long v, float& lo, float& hi) {
    asm("mov.b64 {%0, %1}, %2;" : "=f"(lo), "=f"(hi) : "l"(v));
}

__global__ __launch_bounds__(THREADS, 1)
void performer_kernel(const float* __restrict__ x,
                      const float* __restrict__ proj,
                      float* __restrict__ out,
                      int n_tiles) {
    extern __shared__ float sm[];
    // layout: ps [J][PITCH] (row-permuted), xs [M_TILE][PITCH], sdiag [M_TILE]
    float* ps    = sm;
    float* xs    = sm + J * PITCH;
    float* sdiag = xs + M_TILE * PITCH;

    const int tid = threadIdx.x;

    const float NORM  = 0.3535533905932738f;  // 64^-0.25
    const float RATIO = 0.0625f;              // 256^-0.5
    const float EPSV  = 1e-4f;

    // ---- stage projection ONCE (pre-scaled, row-permuted for conflict-free pv) ----
    // feature j -> smem row s(j): swap the two 2-bit fields inside each 16-row group
    #pragma unroll
    for (int r = 0; r < (J * D) / (THREADS * 4); r++) {   // 8 float4 per thread
        int f  = tid + r * THREADS;                        // float4 index
        int j  = f >> 4;                                   // feature row
        int k0 = (f & 15) << 2;                            // k offset
        int s  = (j & ~15) | ((j & 3) << 2) | ((j >> 2) & 3);
        float4 v = reinterpret_cast<const float4*>(proj)[f];
        v.x *= NORM; v.y *= NORM; v.z *= NORM; v.w *= NORM;
        *reinterpret_cast<float4*>(ps + s * PITCH + k0) = v;
    }

    // thread -> register-tile mapping
    const int lane = tid & 31;
    const int w    = tid >> 5;
    const int tg   = lane & 7;        // token group: tokens tg + 8*i
    const int jg   = lane >> 3;       // feature sub-col
    const int j0   = (w << 4) + (jg << 2);   // 4 consecutive output features

    unsigned sbase;
    asm("{ .reg .u64 t; cvta.to.shared.u64 t, %1; cvt.u32.u64 %0, t; }"
        : "=r"(sbase) : "l"(sm));
    // pv rows for (m): s = w*16 + 4m + jg  (consecutive over jg -> conflict-free v4)
    const unsigned pbase = sbase + (unsigned)(((w << 4) + jg) * PITCH) * 4u;
    const unsigned xs_a  = sbase + (unsigned)(J * PITCH) * 4u;
    const unsigned xbase = xs_a + (unsigned)(tg * PITCH) * 4u;

    for (int tile = blockIdx.x; tile < n_tiles; tile += GRID) {
        const int m0 = tile * M_TILE;
        __syncthreads();   // prior tile's readers done before xs overwrite

        // ---- stage x tile, coalesced float4 ----
        const float* xblk = x + (size_t)m0 * D;
        #pragma unroll
        for (int r = 0; r < (M_TILE * D) / (THREADS * 4); r++) {  // 2 float4/thread
            int f  = tid + r * THREADS;
            int t  = f >> 4;
            int k0 = (f & 15) << 2;
            *reinterpret_cast<float4*>(xs + t * PITCH + k0) =
                reinterpret_cast<const float4*>(xblk)[f];
        }
        __syncthreads();

        // ---- diag = 0.5*||x||^2 : 8 lanes/token, butterfly ----
        {
            const int t  = tid >> 3;
            const int k0 = (tid & 7) * 8;
            float s = 0.f;
            #pragma unroll
            for (int k = 0; k < 8; k++) {
                float v = xs[t * PITCH + k0 + k];
                s += v * v;
            }
            #pragma unroll
            for (int d = 4; d > 0; d >>= 1)
                s += __shfl_xor_sync(0xFFFFFFFFu, s, d);
            if ((tid & 7) == 0) sdiag[t] = 0.5f * s;
        }
        __syncthreads();

        // ---- main loop: 8 tokens x 4 features, f32x2 along K, LDS.128 ----
        unsigned long long acc[8][4];
        #pragma unroll
        for (int i = 0; i < 8; i++)
            #pragma unroll
            for (int m = 0; m < 4; m++) acc[i][m] = 0ull;

        #pragma unroll
        for (int kq = 0; kq < D / 4; kq++) {      // 4 k-values per iter
            const unsigned koff = (unsigned)kq * 16u;
            unsigned long long pa[4], pb[4];
            #pragma unroll
            for (int m = 0; m < 4; m++)
                lds_v2u64(pbase + (unsigned)(m * 4 * PITCH) * 4u + koff,
                          pa[m], pb[m]);
            #pragma unroll
            for (int i = 0; i < 8; i++) {
                unsigned long long xa, xb;
                lds_v2u64(xbase + (unsigned)(i * 8 * PITCH) * 4u + koff, xa, xb);
                #pragma unroll
                for (int m = 0; m < 4; m++) {
                    ffma2(acc[i][m], xa, pa[m]);
                    ffma2(acc[i][m], xb, pb[m]);
                }
            }
        }

        // ---- epilogue: combine halves, exp, float4 store ----
        #pragma unroll
        for (int i = 0; i < 8; i++) {
            const int t = tg + 8 * i;
            const float dg = sdiag[t];
            float r[4];
            #pragma unroll
            for (int m = 0; m < 4; m++) {
                float lo, hi;
                unpack2(acc[i][m], lo, hi);
                float dd = lo + hi;
                r[m] = RATIO * (__expf(dd - dg) + EPSV);
            }
            float4 o = make_float4(r[0], r[1], r[2], r[3]);
            *reinterpret_cast<float4*>(out + (size_t)(m0 + t) * J + j0) = o;
        }
    }
}

extern "C" void kernel_launch(void* const* d_in, const int* in_sizes, int n_in,
                              void* d_out, int out_size) {
    const float* x    = (const float*)d_in[0];   // [2,16,4096,64] fp32
    const float* proj = (const float*)d_in[1];   // [256,64] fp32
    float* out        = (float*)d_out;           // [2,16,4096,256] fp32

    const int M = in_sizes[0] / D;               // 131072 tokens
    const int n_tiles = M / M_TILE;              // 2048
    const int grid = (n_tiles < GRID) ? n_tiles : GRID;

    const int smem_bytes = (J * PITCH + M_TILE * PITCH + M_TILE) * (int)sizeof(float);
    cudaFuncSetAttribute(performer_kernel,
                         cudaFuncAttributeMaxDynamicSharedMemorySize, smem_bytes);

    performer_kernel<<<grid, THREADS, smem_bytes>>>(x, proj, out, n_tiles);
}